// round 16
// baseline (speedup 1.0000x reference)
#include <cuda_runtime.h>
#include <cuda_fp16.h>
#include <cstdint>
#include <cstddef>

// VQ nearest-neighbor quantization: single-split fp16 mma.sync, 2 CTAs/SM,
// software-pipelined tiles (double-buffered A), exact argmin via unmerged
// slot top-2 keys + fp64 near-tie refinement (4 threads/position, ILP-4).
// x: [32,64,64,64] f32 (B,C,H,W), codebook: [512,64] f32
// out: codes [B,C,H,W] f32 (8388608) then indices [B,H,W] as f32 (131072)

#define KCODES 512
#define DCH    64
#define BATCH  32
#define HH     64
#define WW     64
#define THREADS 256
#define POS     64
#define NTILES  (BATCH*HH)       // 2048 (one h-row per tile)
#define BIAS    512.0f
#define MARGIN  0.125f

#define CODES_ELEMS ((size_t)BATCH*DCH*HH*WW)
#define IDX_ELEMS   ((size_t)BATCH*HH*WW)

// ---- smem byte offsets from 1024-aligned base ----
#define A0_OFF   0            // [64][128B] fp16 SW128 (x hi), buffer 0
#define A1_OFF   8192         // buffer 1
#define B_HI_OFF 16384        // [512][128B] fp16 SW128 (cb hi)
#define HB_OFF   81920        // float[512] BIAS - 0.5||c||^2
#define BKS_OFF  83968        // u32[64][17] slot best keys
#define SKS_OFF  88320        // u32[64][17] slot second keys
#define IDXS_OFF 92672        // int[64]
#define SMEM_BYTES (92928 + 1024)

#define SW(o) ((o) ^ (((o) >> 3) & 0x70))

typedef uint32_t u32;

static __device__ __forceinline__ u32 smem_u32(const void* p) {
    u32 a;
    asm("{ .reg .u64 t; cvta.to.shared.u64 t, %1; cvt.u32.u64 %0, t; }" : "=r"(a) : "l"(p));
    return a;
}
static __device__ __forceinline__ u32 pack_h2(float a, float b) {
    __half ha = __float2half(a), hb2 = __float2half(b);
    return (u32)__half_as_ushort(ha) | ((u32)__half_as_ushort(hb2) << 16);
}

#define LDSM_X4(r0,r1,r2,r3, addr) \
    asm volatile("ldmatrix.sync.aligned.m8n8.x4.shared.b16 {%0,%1,%2,%3}, [%4];" \
        : "=r"(r0),"=r"(r1),"=r"(r2),"=r"(r3) : "r"(addr))

#define MMA16816(d, a, b0, b1) \
    asm volatile("mma.sync.aligned.m16n8k16.row.col.f32.f16.f16.f32 " \
        "{%0,%1,%2,%3}, {%4,%5,%6,%7}, {%8,%9}, {%0,%1,%2,%3};" \
        : "+f"((d)[0]),"+f"((d)[1]),"+f"((d)[2]),"+f"((d)[3]) \
        : "r"((a)[0]),"r"((a)[1]),"r"((a)[2]),"r"((a)[3]), "r"(b0),"r"(b1))

// key -> code index; slot = wn*4 + q
static __device__ __forceinline__ int key_to_k(u32 key, int slot) {
    int j5 = 31 - (int)(key & 31u);
    int wn_ = slot >> 2, q_ = slot & 3;
    return 128*wn_ + (j5 >> 3)*32 + ((j5 >> 1) & 3)*8 + 2*q_ + (j5 & 1);
}

__global__ __launch_bounds__(THREADS, 2)
void vq_kernel(const float* __restrict__ x, const float* __restrict__ cb,
               float* __restrict__ out, int write_idx)
{
    extern __shared__ char smraw[];
    const u32 sb0 = smem_u32(smraw);
    const u32 sb  = (sb0 + 1023u) & ~1023u;
    char* base = smraw + (sb - sb0);

    float* hb   = (float*)(base + HB_OFF);
    u32*   bKs  = (u32*)  (base + BKS_OFF);
    u32*   sKs  = (u32*)  (base + SKS_OFF);
    int*   idxs = (int*)  (base + IDXS_OFF);

    const int tid  = threadIdx.x;
    const int wid  = tid >> 5;
    const int lane = tid & 31;
    const int wm   = wid & 1;    // M group: positions 32*wm..+31 (2 groups)
    const int wn   = wid >> 1;   // N group: codes 128*wn..+127 (4 groups)
    const int q    = lane & 3;   // column pair within C frag

    // per-lane ldmatrix geometry (non-trans, proven rounds 10-15)
    const int a_row = (lane & 7) + ((lane >> 3) & 1) * 8;
    const int a_kb  = (lane >> 4) & 1;
    const int b_row = (lane & 7) + ((lane >> 4) & 1) * 8;
    const int b_kb  = (lane >> 3) & 1;
    const u32 xorL  = (u32)((lane & 7) << 4);

    // ---- one-time: codebook -> fp16 hi swizzled SMEM ----
    for (int it = 0; it < 32; it++) {
        int idx = tid + it * THREADS;        // 8192 items: (k, cgroup)
        int k  = idx >> 4;
        int c0 = (idx & 15) * 4;
        float4 v = *(const float4*)(cb + (size_t)k * DCH + c0);
        u32 hi0 = pack_h2(v.x, v.y), hi1 = pack_h2(v.z, v.w);
        u32 o = (u32)(k * 128) + (u32)((c0 * 2) ^ ((k & 7) << 4));
        *(uint2*)(base + B_HI_OFF + o) = make_uint2(hi0, hi1);
    }
    for (int k = tid; k < KCODES; k += THREADS) {
        float s = 0.f;
        #pragma unroll
        for (int c = 0; c < DCH; c++) { float v = cb[(size_t)k * DCH + c]; s += v * v; }
        hb[k] = BIAS - 0.5f * s;
    }

    // ---- prologue: stage first tile into A0 ----
    {
        const int t0 = blockIdx.x;
        const int b  = t0 >> 6;
        const int h  = t0 & 63;
        #pragma unroll
        for (int it = 0; it < 4; it++) {
            int idx = tid + it * THREADS;    // 1024 items
            int p   = idx & 63;
            int c0  = (idx >> 6) * 4;
            const float* gx = x + (((size_t)b * DCH + c0) * HH + h) * WW + p;
            float v0 = gx[0];
            float v1 = gx[(size_t)HH * WW];
            float v2 = gx[(size_t)2 * HH * WW];
            float v3 = gx[(size_t)3 * HH * WW];
            u32 o = (u32)(p * 128) + (u32)((c0 * 2) ^ ((p & 7) << 4));
            *(uint2*)(base + A0_OFF + o) = make_uint2(pack_h2(v0, v1), pack_h2(v2, v3));
        }
    }
    __syncthreads();

    int buf = 0;
    const int gridsz = gridDim.x;

    for (int tile = blockIdx.x; tile < NTILES; tile += gridsz) {
        const int b = tile >> 6;
        const int h = tile & 63;
        const u32 Abase = sb + (buf ? A1_OFF : A0_OFF);

        // ---- mainloop: 4 chunks, single fp16 split; slot top-2 keys ----
        u32 bK[4] = {0u,0u,0u,0u};
        u32 sK[4] = {0u,0u,0u,0u};
        const int m0  = 32 * wm;
        const int nb0 = 128 * wn;

        #pragma unroll
        for (int chunk = 0; chunk < 4; chunk++) {
            float acc[4][2][4];
            #pragma unroll
            for (int ntc = 0; ntc < 4; ntc++) {
                float2 h2 = *(const float2*)(hb + nb0 + chunk * 32 + ntc * 8 + 2 * q);
                #pragma unroll
                for (int mt = 0; mt < 2; mt++) {
                    acc[ntc][mt][0] = h2.x; acc[ntc][mt][1] = h2.y;
                    acc[ntc][mt][2] = h2.x; acc[ntc][mt][3] = h2.y;
                }
            }

            // A fragments once per chunk
            u32 a[2][4][4];
            #pragma unroll
            for (int mt = 0; mt < 2; mt++)
                #pragma unroll
                for (int ks = 0; ks < 4; ks++) {
                    u32 colb = (u32)(ks * 32 + a_kb * 16) ^ xorL;
                    u32 ad = Abase + (u32)((m0 + mt * 16 + a_row) * 128) + colb;
                    LDSM_X4(a[mt][ks][0], a[mt][ks][1], a[mt][ks][2], a[mt][ks][3], ad);
                }

            #pragma unroll
            for (int np = 0; np < 2; np++) {
                const int n0 = nb0 + chunk * 32 + np * 16;
                #pragma unroll
                for (int ks = 0; ks < 4; ks++) {
                    u32 b0, b1, b2, b3;
                    u32 colb = (u32)(ks * 32 + b_kb * 16) ^ xorL;
                    u32 bd = sb + B_HI_OFF + (u32)((n0 + b_row) * 128) + colb;
                    LDSM_X4(b0, b1, b2, b3, bd);
                    #pragma unroll
                    for (int mt = 0; mt < 2; mt++) {
                        MMA16816(acc[np*2+0][mt], a[mt][ks], b0, b1);
                        MMA16816(acc[np*2+1][mt], a[mt][ks], b2, b3);
                    }
                }
            }

            // chunk scoring: quantized keys + branchless slot top-2
            #pragma unroll
            for (int ntc = 0; ntc < 4; ntc++) {
                const int nt = chunk * 4 + ntc;
                const u32 jrL = (u32)(31 - (nt * 2 + 0));
                const u32 jrH = (u32)(31 - (nt * 2 + 1));
                #pragma unroll
                for (int mt = 0; mt < 2; mt++) {
                    u32 k0b = (__float_as_uint(acc[ntc][mt][0]) & ~31u) | jrL;
                    u32 k1b = (__float_as_uint(acc[ntc][mt][1]) & ~31u) | jrH;
                    u32 k2b = (__float_as_uint(acc[ntc][mt][2]) & ~31u) | jrL;
                    u32 k3b = (__float_as_uint(acc[ntc][mt][3]) & ~31u) | jrH;
                    int sA = mt * 2, sB = mt * 2 + 1;
                    sK[sA] = umax(sK[sA], umin(bK[sA], k0b)); bK[sA] = umax(bK[sA], k0b);
                    sK[sA] = umax(sK[sA], umin(bK[sA], k1b)); bK[sA] = umax(bK[sA], k1b);
                    sK[sB] = umax(sK[sB], umin(bK[sB], k2b)); bK[sB] = umax(bK[sB], k2b);
                    sK[sB] = umax(sK[sB], umin(bK[sB], k3b)); bK[sB] = umax(bK[sB], k3b);
                }
            }
        }

        // ---- write per-slot top-2 keys ----
        #pragma unroll
        for (int mt = 0; mt < 2; mt++)
            #pragma unroll
            for (int r = 0; r < 2; r++) {
                int p = m0 + mt * 16 + (lane >> 2) + 8 * r;
                bKs[p * 17 + wn * 4 + q] = bK[mt * 2 + r];
                sKs[p * 17 + wn * 4 + q] = sK[mt * 2 + r];
            }

        // ---- prefetch next tile's x into registers ----
        const int ntile = tile + gridsz;
        const bool havenext = (ntile < NTILES);
        uint2 pf[4];
        if (havenext) {
            const int nb = ntile >> 6;
            const int nh = ntile & 63;
            #pragma unroll
            for (int it = 0; it < 4; it++) {
                int idx = tid + it * THREADS;
                int p   = idx & 63;
                int c0  = (idx >> 6) * 4;
                const float* gx = x + (((size_t)nb * DCH + c0) * HH + nh) * WW + p;
                float v0 = __ldg(gx);
                float v1 = __ldg(gx + (size_t)HH * WW);
                float v2 = __ldg(gx + (size_t)2 * HH * WW);
                float v3 = __ldg(gx + (size_t)3 * HH * WW);
                pf[it] = make_uint2(pack_h2(v0, v1), pack_h2(v2, v3));
            }
        }

        __syncthreads();   // S1: keys visible, A[buf] consumed

        // ---- store prefetched A into alternate buffer ----
        if (havenext) {
            char* Anext = base + (buf ? A0_OFF : A1_OFF);
            #pragma unroll
            for (int it = 0; it < 4; it++) {
                int idx = tid + it * THREADS;
                int p   = idx & 63;
                int c0  = (idx >> 6) * 4;
                u32 o = (u32)(p * 128) + (u32)((c0 * 2) ^ ((p & 7) << 4));
                *(uint2*)(Anext + o) = pf[it];
            }
        }

        // ---- refine: 4 threads per position (group-masked shuffles, ILP-4 fp64) ----
        {
            const int rp = tid >> 2;    // position 0..63
            const int rs = tid & 3;     // sub-scanner
            const unsigned gm = 0xFu << (lane & ~3);
            u32 cand[8];
            #pragma unroll
            for (int j = 0; j < 4; j++) cand[j]     = bKs[rp * 17 + rs * 4 + j];
            #pragma unroll
            for (int j = 0; j < 4; j++) cand[4 + j] = sKs[rp * 17 + rs * 4 + j];

            u32 km = 0;
            #pragma unroll
            for (int j = 0; j < 8; j++) km = umax(km, cand[j]);
            km = umax(km, __shfl_xor_sync(gm, km, 1));
            km = umax(km, __shfl_xor_sync(gm, km, 2));

            float vthr = __uint_as_float(km & ~31u) - BIAS - MARGIN;
            int nf = 0;
            #pragma unroll
            for (int j = 0; j < 8; j++)
                if (__uint_as_float(cand[j] & ~31u) - BIAS >= vthr) nf++;
            nf += __shfl_xor_sync(gm, nf, 1);
            nf += __shfl_xor_sync(gm, nf, 2);

            int bi;
            if (nf <= 1) {
                int lk = 0x7fffffff;
                #pragma unroll
                for (int j = 0; j < 8; j++)
                    if (cand[j] == km) {
                        int kk = key_to_k(cand[j], rs * 4 + (j & 3));
                        lk = min(lk, kk);
                    }
                lk = min(lk, __shfl_xor_sync(gm, lk, 1));
                lk = min(lk, __shfl_xor_sync(gm, lk, 2));
                bi = lk;
            } else {
                const float* gx = x + ((size_t)b * DCH * HH + h) * WW + rp;
                double bd = 1.0e300; int bk = 0x7fffffff;
                #pragma unroll
                for (int j = 0; j < 8; j++) {
                    if (__uint_as_float(cand[j] & ~31u) - BIAS < vthr) continue;
                    int k = key_to_k(cand[j], rs * 4 + (j & 3));
                    const float* crow = cb + (size_t)k * DCH;
                    // 4 independent fp64 chains: latency /4 vs serial accumulation
                    double d0 = 0.0, d1 = 0.0, d2 = 0.0, d3 = 0.0;
                    for (int c = 0; c < DCH; c += 4) {
                        double e0 = (double)__ldg(gx + (size_t)(c+0) * HH * WW) - (double)__ldg(crow + c + 0);
                        double e1 = (double)__ldg(gx + (size_t)(c+1) * HH * WW) - (double)__ldg(crow + c + 1);
                        double e2 = (double)__ldg(gx + (size_t)(c+2) * HH * WW) - (double)__ldg(crow + c + 2);
                        double e3 = (double)__ldg(gx + (size_t)(c+3) * HH * WW) - (double)__ldg(crow + c + 3);
                        d0 += e0 * e0; d1 += e1 * e1; d2 += e2 * e2; d3 += e3 * e3;
                    }
                    double d = (d0 + d1) + (d2 + d3);
                    if (d < bd || (d == bd && k < bk)) { bd = d; bk = k; }
                }
                #pragma unroll
                for (int m = 1; m < 4; m <<= 1) {
                    double od = __shfl_xor_sync(gm, bd, m);
                    int    ok = __shfl_xor_sync(gm, bk, m);
                    if (od < bd || (od == bd && ok < bk)) { bd = od; bk = ok; }
                }
                bi = bk;
            }
            if (rs == 0) idxs[rp] = bi;
        }
        __syncthreads();   // S2: idxs ready, next-A stored

        // ---- epilogue: lane-contiguous w -> fully coalesced 128B stores ----
        {
            const int w  = tid & 63;     // position
            const int cq = tid >> 6;     // channel quarter (16 channels)
            const int k  = idxs[w];
            const float* crow = cb + (size_t)k * DCH + cq * 16;
            float* obase = out + ((size_t)b * DCH + cq * 16) * (HH * WW)
                               + (size_t)h * WW + w;
            #pragma unroll
            for (int e = 0; e < 16; e++) {
                obase[(size_t)e * HH * WW] = __ldg(crow + e);
            }
        }
        if (write_idx && tid < POS) {
            out[CODES_ELEMS + ((size_t)b * HH + h) * WW + tid] = (float)idxs[tid];
        }

        buf ^= 1;
    }
}

extern "C" void kernel_launch(void* const* d_in, const int* in_sizes, int n_in,
                              void* d_out, int out_size)
{
    const float* x  = (const float*)d_in[0];
    const float* cb = (const float*)d_in[1];
    float* out = (float*)d_out;

    int write_idx = ((size_t)out_size >= CODES_ELEMS + IDX_ELEMS) ? 1 : 0;

    int dev = 0;
    cudaGetDevice(&dev);
    int sms = 0;
    cudaDeviceGetAttribute(&sms, cudaDevAttrMultiProcessorCount, dev);
    if (sms <= 0) sms = 148;

    int grid = 2 * sms;                 // 2 CTAs per SM
    if (grid > NTILES) grid = NTILES;

    cudaFuncSetAttribute(vq_kernel, cudaFuncAttributeMaxDynamicSharedMemorySize,
                         (int)SMEM_BYTES);
    vq_kernel<<<grid, THREADS, SMEM_BYTES>>>(x, cb, out, write_idx);
}

// round 17
// speedup vs baseline: 1.2174x; 1.2174x over previous
#include <cuda_runtime.h>
#include <cuda_fp16.h>
#include <cstdint>
#include <cstddef>

// VQ nearest-neighbor quantization: single-split fp16 mma.sync, 2 CTAs/SM,
// software-pipelined tiles (double-buffered A), exact argmin via unmerged
// slot top-2 keys + fp64 near-tie refinement (4 threads/position, ILP-4,
// result consumed from registers - no idx smem round-trip).
// x: [32,64,64,64] f32 (B,C,H,W), codebook: [512,64] f32
// out: codes [B,C,H,W] f32 (8388608) then indices [B,H,W] as f32 (131072)

#define KCODES 512
#define DCH    64
#define BATCH  32
#define HH     64
#define WW     64
#define THREADS 256
#define POS     64
#define NTILES  (BATCH*HH)       // 2048 (one h-row per tile)
#define BIAS    512.0f
#define MARGIN  0.075f

#define CODES_ELEMS ((size_t)BATCH*DCH*HH*WW)
#define IDX_ELEMS   ((size_t)BATCH*HH*WW)

// ---- smem byte offsets from 1024-aligned base ----
#define A0_OFF   0            // [64][128B] fp16 SW128 (x hi), buffer 0
#define A1_OFF   8192         // buffer 1
#define B_HI_OFF 16384        // [512][128B] fp16 SW128 (cb hi)
#define HB_OFF   81920        // float[512] BIAS - 0.5||c||^2
#define BKS_OFF  83968        // u32[64][17] slot best keys
#define SKS_OFF  88320        // u32[64][17] slot second keys
#define SMEM_BYTES (92672 + 1024)

#define SW(o) ((o) ^ (((o) >> 3) & 0x70))

typedef uint32_t u32;

static __device__ __forceinline__ u32 smem_u32(const void* p) {
    u32 a;
    asm("{ .reg .u64 t; cvta.to.shared.u64 t, %1; cvt.u32.u64 %0, t; }" : "=r"(a) : "l"(p));
    return a;
}
static __device__ __forceinline__ u32 pack_h2(float a, float b) {
    __half ha = __float2half(a), hb2 = __float2half(b);
    return (u32)__half_as_ushort(ha) | ((u32)__half_as_ushort(hb2) << 16);
}

#define LDSM_X4(r0,r1,r2,r3, addr) \
    asm volatile("ldmatrix.sync.aligned.m8n8.x4.shared.b16 {%0,%1,%2,%3}, [%4];" \
        : "=r"(r0),"=r"(r1),"=r"(r2),"=r"(r3) : "r"(addr))

#define MMA16816(d, a, b0, b1) \
    asm volatile("mma.sync.aligned.m16n8k16.row.col.f32.f16.f16.f32 " \
        "{%0,%1,%2,%3}, {%4,%5,%6,%7}, {%8,%9}, {%0,%1,%2,%3};" \
        : "+f"((d)[0]),"+f"((d)[1]),"+f"((d)[2]),"+f"((d)[3]) \
        : "r"((a)[0]),"r"((a)[1]),"r"((a)[2]),"r"((a)[3]), "r"(b0),"r"(b1))

// key -> code index; slot = wn*4 + q
static __device__ __forceinline__ int key_to_k(u32 key, int slot) {
    int j5 = 31 - (int)(key & 31u);
    int wn_ = slot >> 2, q_ = slot & 3;
    return 128*wn_ + (j5 >> 3)*32 + ((j5 >> 1) & 3)*8 + 2*q_ + (j5 & 1);
}

__global__ __launch_bounds__(THREADS, 2)
void vq_kernel(const float* __restrict__ x, const float* __restrict__ cb,
               float* __restrict__ out, int write_idx)
{
    extern __shared__ char smraw[];
    const u32 sb0 = smem_u32(smraw);
    const u32 sb  = (sb0 + 1023u) & ~1023u;
    char* base = smraw + (sb - sb0);

    float* hb   = (float*)(base + HB_OFF);
    u32*   bKs  = (u32*)  (base + BKS_OFF);
    u32*   sKs  = (u32*)  (base + SKS_OFF);

    const int tid  = threadIdx.x;
    const int wid  = tid >> 5;
    const int lane = tid & 31;
    const int wm   = wid & 1;    // M group: positions 32*wm..+31
    const int wn   = wid >> 1;   // N group: codes 128*wn..+127
    const int q    = lane & 3;   // column pair within C frag

    // per-lane ldmatrix geometry (non-trans, proven rounds 10-16)
    const int a_row = (lane & 7) + ((lane >> 3) & 1) * 8;
    const int a_kb  = (lane >> 4) & 1;
    const int b_row = (lane & 7) + ((lane >> 4) & 1) * 8;
    const int b_kb  = (lane >> 3) & 1;
    const u32 xorL  = (u32)((lane & 7) << 4);

    // ---- one-time: codebook -> fp16 hi swizzled SMEM ----
    for (int it = 0; it < 32; it++) {
        int idx = tid + it * THREADS;        // 8192 items: (k, cgroup)
        int k  = idx >> 4;
        int c0 = (idx & 15) * 4;
        float4 v = *(const float4*)(cb + (size_t)k * DCH + c0);
        u32 hi0 = pack_h2(v.x, v.y), hi1 = pack_h2(v.z, v.w);
        u32 o = (u32)(k * 128) + (u32)((c0 * 2) ^ ((k & 7) << 4));
        *(uint2*)(base + B_HI_OFF + o) = make_uint2(hi0, hi1);
    }
    for (int k = tid; k < KCODES; k += THREADS) {
        float s = 0.f;
        #pragma unroll
        for (int c = 0; c < DCH; c++) { float v = cb[(size_t)k * DCH + c]; s += v * v; }
        hb[k] = BIAS - 0.5f * s;
    }

    // ---- prologue: stage first tile into A0 ----
    {
        const int t0 = blockIdx.x;
        const int b  = t0 >> 6;
        const int h  = t0 & 63;
        #pragma unroll
        for (int it = 0; it < 4; it++) {
            int idx = tid + it * THREADS;    // 1024 items
            int p   = idx & 63;
            int c0  = (idx >> 6) * 4;
            const float* gx = x + (((size_t)b * DCH + c0) * HH + h) * WW + p;
            float v0 = gx[0];
            float v1 = gx[(size_t)HH * WW];
            float v2 = gx[(size_t)2 * HH * WW];
            float v3 = gx[(size_t)3 * HH * WW];
            u32 o = (u32)(p * 128) + (u32)((c0 * 2) ^ ((p & 7) << 4));
            *(uint2*)(base + A0_OFF + o) = make_uint2(pack_h2(v0, v1), pack_h2(v2, v3));
        }
    }
    __syncthreads();

    int buf = 0;
    const int gridsz = gridDim.x;

    for (int tile = blockIdx.x; tile < NTILES; tile += gridsz) {
        const int b = tile >> 6;
        const int h = tile & 63;
        const u32 Abase = sb + (buf ? A1_OFF : A0_OFF);

        // ---- mainloop: 4 chunks, single fp16 split; slot top-2 keys ----
        u32 bK[4] = {0u,0u,0u,0u};
        u32 sK[4] = {0u,0u,0u,0u};
        const int m0  = 32 * wm;
        const int nb0 = 128 * wn;

        #pragma unroll
        for (int chunk = 0; chunk < 4; chunk++) {
            float acc[4][2][4];
            #pragma unroll
            for (int ntc = 0; ntc < 4; ntc++) {
                float2 h2 = *(const float2*)(hb + nb0 + chunk * 32 + ntc * 8 + 2 * q);
                #pragma unroll
                for (int mt = 0; mt < 2; mt++) {
                    acc[ntc][mt][0] = h2.x; acc[ntc][mt][1] = h2.y;
                    acc[ntc][mt][2] = h2.x; acc[ntc][mt][3] = h2.y;
                }
            }

            // A fragments once per chunk
            u32 a[2][4][4];
            #pragma unroll
            for (int mt = 0; mt < 2; mt++)
                #pragma unroll
                for (int ks = 0; ks < 4; ks++) {
                    u32 colb = (u32)(ks * 32 + a_kb * 16) ^ xorL;
                    u32 ad = Abase + (u32)((m0 + mt * 16 + a_row) * 128) + colb;
                    LDSM_X4(a[mt][ks][0], a[mt][ks][1], a[mt][ks][2], a[mt][ks][3], ad);
                }

            #pragma unroll
            for (int np = 0; np < 2; np++) {
                const int n0 = nb0 + chunk * 32 + np * 16;
                #pragma unroll
                for (int ks = 0; ks < 4; ks++) {
                    u32 b0, b1, b2, b3;
                    u32 colb = (u32)(ks * 32 + b_kb * 16) ^ xorL;
                    u32 bd = sb + B_HI_OFF + (u32)((n0 + b_row) * 128) + colb;
                    LDSM_X4(b0, b1, b2, b3, bd);
                    #pragma unroll
                    for (int mt = 0; mt < 2; mt++) {
                        MMA16816(acc[np*2+0][mt], a[mt][ks], b0, b1);
                        MMA16816(acc[np*2+1][mt], a[mt][ks], b2, b3);
                    }
                }
            }

            // chunk scoring: quantized keys + branchless slot top-2
            #pragma unroll
            for (int ntc = 0; ntc < 4; ntc++) {
                const int nt = chunk * 4 + ntc;
                const u32 jrL = (u32)(31 - (nt * 2 + 0));
                const u32 jrH = (u32)(31 - (nt * 2 + 1));
                #pragma unroll
                for (int mt = 0; mt < 2; mt++) {
                    u32 k0b = (__float_as_uint(acc[ntc][mt][0]) & ~31u) | jrL;
                    u32 k1b = (__float_as_uint(acc[ntc][mt][1]) & ~31u) | jrH;
                    u32 k2b = (__float_as_uint(acc[ntc][mt][2]) & ~31u) | jrL;
                    u32 k3b = (__float_as_uint(acc[ntc][mt][3]) & ~31u) | jrH;
                    int sA = mt * 2, sB = mt * 2 + 1;
                    sK[sA] = umax(sK[sA], umin(bK[sA], k0b)); bK[sA] = umax(bK[sA], k0b);
                    sK[sA] = umax(sK[sA], umin(bK[sA], k1b)); bK[sA] = umax(bK[sA], k1b);
                    sK[sB] = umax(sK[sB], umin(bK[sB], k2b)); bK[sB] = umax(bK[sB], k2b);
                    sK[sB] = umax(sK[sB], umin(bK[sB], k3b)); bK[sB] = umax(bK[sB], k3b);
                }
            }
        }

        // ---- write per-slot top-2 keys ----
        #pragma unroll
        for (int mt = 0; mt < 2; mt++)
            #pragma unroll
            for (int r = 0; r < 2; r++) {
                int p = m0 + mt * 16 + (lane >> 2) + 8 * r;
                bKs[p * 17 + wn * 4 + q] = bK[mt * 2 + r];
                sKs[p * 17 + wn * 4 + q] = sK[mt * 2 + r];
            }

        // ---- prefetch next tile's x into registers ----
        const int ntile = tile + gridsz;
        const bool havenext = (ntile < NTILES);
        uint2 pf[4];
        if (havenext) {
            const int nb = ntile >> 6;
            const int nh = ntile & 63;
            #pragma unroll
            for (int it = 0; it < 4; it++) {
                int idx = tid + it * THREADS;
                int p   = idx & 63;
                int c0  = (idx >> 6) * 4;
                const float* gx = x + (((size_t)nb * DCH + c0) * HH + nh) * WW + p;
                float v0 = __ldg(gx);
                float v1 = __ldg(gx + (size_t)HH * WW);
                float v2 = __ldg(gx + (size_t)2 * HH * WW);
                float v3 = __ldg(gx + (size_t)3 * HH * WW);
                pf[it] = make_uint2(pack_h2(v0, v1), pack_h2(v2, v3));
            }
        }

        __syncthreads();   // S1: keys visible, A[buf] consumed

        // ---- store prefetched A into alternate buffer ----
        if (havenext) {
            char* Anext = base + (buf ? A0_OFF : A1_OFF);
            #pragma unroll
            for (int it = 0; it < 4; it++) {
                int idx = tid + it * THREADS;
                int p   = idx & 63;
                int c0  = (idx >> 6) * 4;
                u32 o = (u32)(p * 128) + (u32)((c0 * 2) ^ ((p & 7) << 4));
                *(uint2*)(Anext + o) = pf[it];
            }
        }

        // ---- refine: 4 threads per position (group-masked shuffles, ILP-4 fp64)
        //      result bi stays in registers; epilogue follows immediately ----
        {
            const int rp = tid >> 2;    // position 0..63
            const int rs = tid & 3;     // sub-scanner
            const unsigned gm = 0xFu << (lane & ~3);
            u32 cand[8];
            #pragma unroll
            for (int j = 0; j < 4; j++) cand[j]     = bKs[rp * 17 + rs * 4 + j];
            #pragma unroll
            for (int j = 0; j < 4; j++) cand[4 + j] = sKs[rp * 17 + rs * 4 + j];

            u32 km = 0;
            #pragma unroll
            for (int j = 0; j < 8; j++) km = umax(km, cand[j]);
            km = umax(km, __shfl_xor_sync(gm, km, 1));
            km = umax(km, __shfl_xor_sync(gm, km, 2));

            float vthr = __uint_as_float(km & ~31u) - BIAS - MARGIN;
            int nf = 0;
            #pragma unroll
            for (int j = 0; j < 8; j++)
                if (__uint_as_float(cand[j] & ~31u) - BIAS >= vthr) nf++;
            nf += __shfl_xor_sync(gm, nf, 1);
            nf += __shfl_xor_sync(gm, nf, 2);

            int bi;
            if (nf <= 1) {
                int lk = 0x7fffffff;
                #pragma unroll
                for (int j = 0; j < 8; j++)
                    if (cand[j] == km) {
                        int kk = key_to_k(cand[j], rs * 4 + (j & 3));
                        lk = min(lk, kk);
                    }
                lk = min(lk, __shfl_xor_sync(gm, lk, 1));
                lk = min(lk, __shfl_xor_sync(gm, lk, 2));
                bi = lk;
            } else {
                const float* gx = x + ((size_t)b * DCH * HH + h) * WW + rp;
                double bd = 1.0e300; int bk = 0x7fffffff;
                #pragma unroll
                for (int j = 0; j < 8; j++) {
                    if (__uint_as_float(cand[j] & ~31u) - BIAS < vthr) continue;
                    int k = key_to_k(cand[j], rs * 4 + (j & 3));
                    const float* crow = cb + (size_t)k * DCH;
                    // 4 independent fp64 chains: latency /4 vs serial accumulation
                    double d0 = 0.0, d1 = 0.0, d2 = 0.0, d3 = 0.0;
                    for (int c = 0; c < DCH; c += 4) {
                        double e0 = (double)__ldg(gx + (size_t)(c+0) * HH * WW) - (double)__ldg(crow + c + 0);
                        double e1 = (double)__ldg(gx + (size_t)(c+1) * HH * WW) - (double)__ldg(crow + c + 1);
                        double e2 = (double)__ldg(gx + (size_t)(c+2) * HH * WW) - (double)__ldg(crow + c + 2);
                        double e3 = (double)__ldg(gx + (size_t)(c+3) * HH * WW) - (double)__ldg(crow + c + 3);
                        d0 += e0 * e0; d1 += e1 * e1; d2 += e2 * e2; d3 += e3 * e3;
                    }
                    double d = (d0 + d1) + (d2 + d3);
                    if (d < bd || (d == bd && k < bk)) { bd = d; bk = k; }
                }
                #pragma unroll
                for (int m = 1; m < 4; m <<= 1) {
                    double od = __shfl_xor_sync(gm, bd, m);
                    int    ok = __shfl_xor_sync(gm, bk, m);
                    if (od < bd || (od == bd && ok < bk)) { bd = od; bk = ok; }
                }
                bi = bk;
            }

            // ---- epilogue (register bi, round-15 addressing): thread (rp, rs)
            //      writes channels rs*16..+15 for position rp ----
            {
                const float4* crow = (const float4*)(cb + (size_t)bi * DCH + rs * 16);
                float* obase = out + ((size_t)b * DCH + rs * 16) * (HH * WW)
                                   + (size_t)h * WW + rp;
                #pragma unroll
                for (int e = 0; e < 4; e++) {
                    float4 v = __ldg(crow + e);
                    obase[(size_t)(e * 4 + 0) * HH * WW] = v.x;
                    obase[(size_t)(e * 4 + 1) * HH * WW] = v.y;
                    obase[(size_t)(e * 4 + 2) * HH * WW] = v.z;
                    obase[(size_t)(e * 4 + 3) * HH * WW] = v.w;
                }
                if (write_idx && rs == 0) {
                    out[CODES_ELEMS + ((size_t)b * HH + h) * WW + rp] = (float)bi;
                }
            }
        }

        __syncthreads();   // S2: bKs/sKs reusable, next-A stores visible

        buf ^= 1;
    }
}

extern "C" void kernel_launch(void* const* d_in, const int* in_sizes, int n_in,
                              void* d_out, int out_size)
{
    const float* x  = (const float*)d_in[0];
    const float* cb = (const float*)d_in[1];
    float* out = (float*)d_out;

    int write_idx = ((size_t)out_size >= CODES_ELEMS + IDX_ELEMS) ? 1 : 0;

    int dev = 0;
    cudaGetDevice(&dev);
    int sms = 0;
    cudaDeviceGetAttribute(&sms, cudaDevAttrMultiProcessorCount, dev);
    if (sms <= 0) sms = 148;

    int grid = 2 * sms;                 // 2 CTAs per SM
    if (grid > NTILES) grid = NTILES;

    cudaFuncSetAttribute(vq_kernel, cudaFuncAttributeMaxDynamicSharedMemorySize,
                         (int)SMEM_BYTES);
    vq_kernel<<<grid, THREADS, SMEM_BYTES>>>(x, cb, out, write_idx);
}